// round 12
// baseline (speedup 1.0000x reference)
#include <cuda_runtime.h>
#include <cuda_bf16.h>
#include <cuda_fp16.h>
#include <stdint.h>

// Problem constants (fixed by the reference)
#define NNODES 50000
#define NEDGES 800000
#define KDIM   512
#define HDIM   128

#define SCAN_BLK 256
#define N_SCAN_BLOCKS ((NNODES + SCAN_BLK - 1) / SCAN_BLK)   // 196

#define CSR_BLOCKS  1184                 // 8 blocks/SM x 148 SMs, all resident
#define CSR_THREADS (CSR_BLOCKS * 256)

#define BK 32
#define KB_ITERS (KDIM / BK)           // 16
#define N_TILES ((NNODES + 127) / 128) // 391
#define WB_U32  (KB_ITERS * 2048)      // W fp16 tiles: 16 x 8KB = 32K u32

// ---------------- device scratch (no allocs allowed) ----------------
__device__ uint32_t g_h2[NNODES * 64];      // h = x @ W, fp16 half2-packed
__device__ int      g_cnt[NNODES];          // zeroed by csr kernel for next run
__device__ int      g_off[NNODES + 1];
__device__ int      g_cursor[NNODES];       // zeroed by csr kernel for next run
__device__ int      g_srcs[NEDGES];
__device__ float    g_dinv[NNODES];
__device__ int      g_bsum[N_SCAN_BLOCKS];
__device__ int      g_done;                 // monotonic grid-barrier counter (self-reset)
// W as fp16, per-kb tiles [n=128][64B row: k0-31], SW64-swizzled:
__device__ uint32_t g_Wb[WB_U32];

// ======================= PTX helpers (baseline compute_103-safe) ==========
__device__ __forceinline__ uint32_t smem_u32(const void* p) {
    uint32_t a;
    asm("{ .reg .u64 t; cvta.to.shared.u64 t, %1; cvt.u32.u64 %0, t; }"
        : "=r"(a) : "l"(p));
    return a;
}
__device__ __forceinline__ uint32_t sw64(uint32_t off) {
    return off ^ ((off >> 3) & 0x30);
}
__device__ __forceinline__ void ldsm_x4(uint32_t& r0, uint32_t& r1,
                                        uint32_t& r2, uint32_t& r3, uint32_t addr) {
    asm volatile("ldmatrix.sync.aligned.m8n8.x4.shared.b16 {%0,%1,%2,%3}, [%4];"
        : "=r"(r0), "=r"(r1), "=r"(r2), "=r"(r3) : "r"(addr));
}
__device__ __forceinline__ void mma_fp16(float* c, const uint32_t* a,
                                         uint32_t b0, uint32_t b1) {
    asm volatile(
        "mma.sync.aligned.m16n8k16.row.col.f32.f16.f16.f32 "
        "{%0,%1,%2,%3}, {%4,%5,%6,%7}, {%8,%9}, {%0,%1,%2,%3};"
        : "+f"(c[0]), "+f"(c[1]), "+f"(c[2]), "+f"(c[3])
        : "r"(a[0]), "r"(a[1]), "r"(a[2]), "r"(a[3]), "r"(b0), "r"(b1));
}
__device__ __forceinline__ void cp_async16(uint32_t smem_dst, const void* gsrc) {
    asm volatile("cp.async.cg.shared.global [%0], [%1], 16;"
        :: "r"(smem_dst), "l"(gsrc) : "memory");
}
__device__ __forceinline__ void cp_async16_z(uint32_t smem_dst, const void* gsrc,
                                             uint32_t srcsz) {
    asm volatile("cp.async.cg.shared.global [%0], [%1], 16, %2;"
        :: "r"(smem_dst), "l"(gsrc), "r"(srcsz) : "memory");
}
#define CP_COMMIT() asm volatile("cp.async.commit_group;" ::: "memory")
#define CP_WAIT(n)  asm volatile("cp.async.wait_group %0;" :: "n"(n) : "memory")
__device__ __forceinline__ uint4 lds128(uint32_t a) {
    uint4 v;
    asm volatile("ld.shared.v4.u32 {%0,%1,%2,%3}, [%4];"
        : "=r"(v.x), "=r"(v.y), "=r"(v.z), "=r"(v.w) : "r"(a));
    return v;
}
__device__ __forceinline__ void sts128u(uint32_t a, uint4 v) {
    asm volatile("st.shared.v4.u32 [%0], {%1,%2,%3,%4};"
        :: "r"(a), "r"(v.x), "r"(v.y), "r"(v.z), "r"(v.w) : "memory");
}
__device__ __forceinline__ uint32_t f16x2_rn(float lo, float hi) {
    uint32_t r;
    asm("cvt.rn.f16x2.f32 %0, %1, %2;" : "=r"(r) : "f"(hi), "f"(lo));
    return r;
}

// ============================================================================
// Kernel 0: W -> fp16 tiles, per-kb [n=128][64B: k0-31], SW64-swizzled.
// ============================================================================
__global__ __launch_bounds__(256)
void wprep_kernel(const float* __restrict__ W)
{
    int o = blockIdx.x * blockDim.x + threadIdx.x;
    if (o >= WB_U32) return;
    int kb = o >> 11;
    uint32_t byte = (o & 2047) * 4;
    uint32_t un = sw64(byte);
    int n = un >> 6;
    int i = (un & 63) >> 2;
    int k0 = kb * BK + 2 * i;
    float w0 = W[(size_t)k0 * HDIM + n];
    float w1 = W[(size_t)(k0 + 1) * HDIM + n];
    g_Wb[o] = f16x2_rn(w0, w1);
}

// ============================================================================
// Kernel 1: fp16 GEMM via mma.sync m16n8k16 (f32 accumulate).
// CTA 128x128, 256 threads, warp tile 32x64. 3-stage cp.async pipeline
// (82 KB SMEM -> 2 CTAs/SM — round-9 known-good configuration, unchanged).
// ============================================================================
__global__ __launch_bounds__(256, 2)
void gemm_tc_kernel(const float* __restrict__ X)
{
    extern __shared__ char dsm[];
    const uint32_t base = (smem_u32(dsm) + 1023u) & ~1023u;
    uint32_t RA[3] = { base, base + 16384, base + 32768 };       // raw f32 stages
    uint32_t BB[3] = { base + 49152, base + 57344, base + 65536 }; // fp16 W stages
    const uint32_t AB = base + 73728;                             // fp16 A tile

    const int tid  = threadIdx.x;
    const int lane = tid & 31;
    const int wid  = tid >> 5;
    const int wm   = wid >> 1;
    const int wn   = wid & 1;
    const int brow = blockIdx.x * 128;

    // ---- raw-A cp.async assignment: 4 x 16B per thread (SW128 rows) ----
    uint32_t a_dst[4];
    const float* a_srcb[4];
    uint32_t a_sz[4];
    #pragma unroll
    for (int i = 0; i < 4; i++) {
        int idx = tid + i * 256;
        int row = idx >> 3;
        int q   = idx & 7;
        a_dst[i]  = (uint32_t)row * 128 + ((uint32_t)(q ^ (row & 7)) << 4);
        a_srcb[i] = X + (size_t)(brow + row) * KDIM + q * 4;
        a_sz[i]   = ((brow + row) < NNODES) ? 16u : 0u;
    }

    // ---- convert-pass assignment: 2 output 16B groups per thread ----
    uint32_t c_src[2][2], c_dst[2];
    #pragma unroll
    for (int i = 0; i < 2; i++) {
        int slot = tid + i * 256;
        int row  = slot >> 2;
        int og   = slot & 3;
        uint32_t rx = (uint32_t)(row & 7);
        c_src[i][0] = (uint32_t)row * 128 + (((uint32_t)(2 * og)     ^ rx) << 4);
        c_src[i][1] = (uint32_t)row * 128 + (((uint32_t)(2 * og + 1) ^ rx) << 4);
        c_dst[i]    = (uint32_t)row * 64 +
                      (((uint32_t)og ^ ((uint32_t)(row >> 1) & 3)) << 4);
    }

    // ---- ldmatrix address precompute (64B rows, SW64) ----
    uint32_t a_rb[2], a_rx[2];
    #pragma unroll
    for (int mf = 0; mf < 2; mf++) {
        uint32_t row = wm * 32 + mf * 16 + (lane & 15);
        a_rb[mf] = row * 64;
        a_rx[mf] = (row >> 1) & 3;
    }
    const uint32_t a_cbase = (uint32_t)(lane >> 4);
    uint32_t b_rb[4], b_rx[4];
    #pragma unroll
    for (int p = 0; p < 4; p++) {
        uint32_t n = wn * 64 + p * 16 + ((lane >> 4) << 3) + (lane & 7);
        b_rb[p] = n * 64;
        b_rx[p] = (n >> 1) & 3;
    }
    const uint32_t b_cbase = (uint32_t)((lane >> 3) & 1);

    float acc[2][8][4];
    #pragma unroll
    for (int mf = 0; mf < 2; mf++)
        #pragma unroll
        for (int nf = 0; nf < 8; nf++)
            #pragma unroll
            for (int j = 0; j < 4; j++) acc[mf][nf][j] = 0.f;

    // ---- stage helper (stage s into buffer s%3), one commit per stage ----
    auto stage = [&](int s) {
        uint32_t ra = RA[s % 3], bb = BB[s % 3];
        const uint32_t* wb = g_Wb + (size_t)s * 2048;
        #pragma unroll
        for (int i = 0; i < 4; i++)
            cp_async16_z(ra + a_dst[i], a_srcb[i] + s * BK, a_sz[i]);
        #pragma unroll
        for (int i = 0; i < 2; i++) {
            int idx = tid + i * 256;
            cp_async16(bb + idx * 16, wb + idx * 4);
        }
        CP_COMMIT();
    };

    // ---- prologue: stages 0 and 1 in flight ----
    stage(0);
    stage(1);

    for (int kb = 0; kb < KB_ITERS; kb++) {
        if (kb + 1 < KB_ITERS) { CP_WAIT(1); } else { CP_WAIT(0); }
        __syncthreads();   // stage kb visible; AB free (prev compute done)

        const uint32_t RAc = RA[kb % 3];
        const uint32_t BBc = BB[kb % 3];

        // ---- convert raw f32 -> fp16 tile AB ----
        #pragma unroll
        for (int i = 0; i < 2; i++) {
            uint4 a = lds128(RAc + c_src[i][0]);
            uint4 b = lds128(RAc + c_src[i][1]);
            uint4 o;
            o.x = f16x2_rn(__uint_as_float(a.x), __uint_as_float(a.y));
            o.y = f16x2_rn(__uint_as_float(a.z), __uint_as_float(a.w));
            o.z = f16x2_rn(__uint_as_float(b.x), __uint_as_float(b.y));
            o.w = f16x2_rn(__uint_as_float(b.z), __uint_as_float(b.w));
            sts128u(AB + c_dst[i], o);
        }
        __syncthreads();   // AB visible; RA[kb] reads done

        // ---- keep 2 stages in flight ----
        if (kb + 2 < KB_ITERS) stage(kb + 2);

        // ---- compute: 2 k16-steps, single fp16 pass ----
        #pragma unroll
        for (int s = 0; s < 2; s++) {
            uint32_t ah[2][4];
            #pragma unroll
            for (int mf = 0; mf < 2; mf++) {
                uint32_t g = (uint32_t)(s * 2) + a_cbase;
                uint32_t off = a_rb[mf] + ((g ^ a_rx[mf]) << 4);
                ldsm_x4(ah[mf][0], ah[mf][1], ah[mf][2], ah[mf][3], AB + off);
            }
            #pragma unroll
            for (int p = 0; p < 4; p++) {
                uint32_t g = (uint32_t)(s * 2) + b_cbase;
                uint32_t off = b_rb[p] + ((g ^ b_rx[p]) << 4);
                uint32_t bh[4];
                ldsm_x4(bh[0], bh[1], bh[2], bh[3], BBc + off);
                #pragma unroll
                for (int j = 0; j < 2; j++) {
                    #pragma unroll
                    for (int mf = 0; mf < 2; mf++)
                        mma_fp16(acc[mf][p * 2 + j], ah[mf],
                                 bh[2 * j], bh[2 * j + 1]);
                }
            }
        }
    }

    // ---- epilogue: accum regs -> g_h2 (fp16 half2-packed) ----
    half2* H2 = (half2*)g_h2;
    #pragma unroll
    for (int mf = 0; mf < 2; mf++) {
        int row0 = brow + wm * 32 + mf * 16 + (lane >> 2);
        #pragma unroll
        for (int nf = 0; nf < 8; nf++) {
            int c2 = wn * 32 + nf * 4 + (lane & 3);
            if (row0 < NNODES)
                H2[(size_t)row0 * 64 + c2] =
                    __floats2half2_rn(acc[mf][nf][0], acc[mf][nf][1]);
            if (row0 + 8 < NNODES)
                H2[(size_t)(row0 + 8) * 64 + c2] =
                    __floats2half2_rn(acc[mf][nf][2], acc[mf][nf][3]);
        }
    }
}

// ============================================================================
// Kernel 2: fused CSR build — hist + scan + fill in ONE persistent kernel.
// 1184 blocks (8/SM x 148, all co-resident) with monotonic grid barriers.
// g_done self-resets on the final arrival -> deterministic across replays.
// ============================================================================
__device__ __forceinline__ void grid_bar(int target)
{
    __syncthreads();
    if (threadIdx.x == 0) {
        __threadfence();
        atomicAdd(&g_done, 1);
        volatile int* dp = &g_done;
        while (*dp < target) { }
    }
    __syncthreads();
    __threadfence();
}

__global__ __launch_bounds__(256)
void csr_kernel(const int* __restrict__ src, const int* __restrict__ dst)
{
    __shared__ int sh[SCAN_BLK];
    __shared__ int red[SCAN_BLK];
    const int t   = threadIdx.x;
    const int blk = blockIdx.x;
    const int gid = blk * 256 + t;

    // ---- phase A: in-degree histogram ----
    for (int e = gid; e < NEDGES; e += CSR_THREADS)
        atomicAdd(&g_cnt[dst[e]], 1);
    grid_bar(CSR_BLOCKS);

    // ---- phase B: scan (blocks 0..195 carry data; others just barrier) ----
    int v = 0;
    if (gid < NNODES) {
        v = g_cnt[gid];
        g_dinv[gid]   = rsqrtf((float)(v + 1));
        g_cnt[gid]    = 0;   // self-clean for next replay
        g_cursor[gid] = 0;
    }
    if (blk < N_SCAN_BLOCKS) {
        sh[t] = v;
        __syncthreads();
        #pragma unroll
        for (int d = 1; d < SCAN_BLK; d <<= 1) {
            int u = (t >= d) ? sh[t - d] : 0;
            __syncthreads();
            sh[t] += u;
            __syncthreads();
        }
        if (t == SCAN_BLK - 1) g_bsum[blk] = sh[t];
    }
    grid_bar(2 * CSR_BLOCKS);

    if (blk < N_SCAN_BLOCKS) {
        red[t] = (t < blk) ? g_bsum[t] : 0;
        __syncthreads();
        #pragma unroll
        for (int d = SCAN_BLK / 2; d > 0; d >>= 1) {
            if (t < d) red[t] += red[t + d];
            __syncthreads();
        }
        if (gid < NNODES) g_off[gid] = (sh[t] - v) + red[0];
        if (gid == 0) g_off[NNODES] = NEDGES;
    }
    grid_bar(3 * CSR_BLOCKS);

    // ---- phase C: fill CSR ----
    for (int e = gid; e < NEDGES; e += CSR_THREADS) {
        int d = dst[e];
        int p = atomicAdd(&g_cursor[d], 1);
        g_srcs[g_off[d] + p] = src[e];
    }

    // ---- final arrival: last one resets the barrier counter ----
    __syncthreads();
    if (t == 0) {
        __threadfence();
        int prev = atomicAdd(&g_done, 1);
        if (prev == 4 * CSR_BLOCKS - 1) g_done = 0;
    }
}

// ============================================================================
// Kernel 3: aggregate + bias + PReLU. One warp per node, fp16 gather.
// (round-9 form: dinv loaded per edge; no g_wts)
// ============================================================================
__device__ __forceinline__ float4 h4_at(const uint2* h2, int node, int lane)
{
    uint2 v = h2[(size_t)node * 32 + lane];
    float2 f = __half22float2(*(const half2*)&v.x);
    float2 g = __half22float2(*(const half2*)&v.y);
    return make_float4(f.x, f.y, g.x, g.y);
}

__global__ __launch_bounds__(256)
void aggregate_kernel(const float* __restrict__ b,
                      const float* __restrict__ pw,
                      float* __restrict__ out)
{
    int gwarp = (blockIdx.x * blockDim.x + threadIdx.x) >> 5;
    int lane  = threadIdx.x & 31;
    if (gwarp >= NNODES) return;

    const uint2* h2 = (const uint2*)g_h2;
    const int n = gwarp;

    float di = g_dinv[n];
    float4 hn = h4_at(h2, n, lane);

    float4 acc = make_float4(0.f, 0.f, 0.f, 0.f);
    int s = g_off[n];
    int e = g_off[n + 1];

    int i = s;
    for (; i + 3 < e; i += 4) {
        int u0 = g_srcs[i];
        int u1 = g_srcs[i + 1];
        int u2 = g_srcs[i + 2];
        int u3 = g_srcs[i + 3];
        float w0 = g_dinv[u0], w1 = g_dinv[u1];
        float w2 = g_dinv[u2], w3 = g_dinv[u3];
        float4 v0 = h4_at(h2, u0, lane);
        float4 v1 = h4_at(h2, u1, lane);
        float4 v2 = h4_at(h2, u2, lane);
        float4 v3 = h4_at(h2, u3, lane);
        acc.x += v0.x * w0 + v1.x * w1 + v2.x * w2 + v3.x * w3;
        acc.y += v0.y * w0 + v1.y * w1 + v2.y * w2 + v3.y * w3;
        acc.z += v0.z * w0 + v1.z * w1 + v2.z * w2 + v3.z * w3;
        acc.w += v0.w * w0 + v1.w * w1 + v2.w * w2 + v3.w * w3;
    }
    for (; i < e; i++) {
        int u = g_srcs[i];
        float w = g_dinv[u];
        float4 v = h4_at(h2, u, lane);
        acc.x += v.x * w; acc.y += v.y * w; acc.z += v.z * w; acc.w += v.w * w;
    }

    float s2 = di * di;
    float4 bb = ((const float4*)b)[lane];
    float4 pp = ((const float4*)pw)[lane];
    float4 r;
    r.x = acc.x * di + hn.x * s2 + bb.x;
    r.y = acc.y * di + hn.y * s2 + bb.y;
    r.z = acc.z * di + hn.z * s2 + bb.z;
    r.w = acc.w * di + hn.w * s2 + bb.w;
    r.x = (r.x > 0.f) ? r.x : r.x * pp.x;
    r.y = (r.y > 0.f) ? r.y : r.y * pp.y;
    r.z = (r.z > 0.f) ? r.z : r.z * pp.z;
    r.w = (r.w > 0.f) ? r.w : r.w * pp.w;

    ((float4*)out)[(size_t)n * 32 + lane] = r;
}

// ============================================================================
// Launch: 5 kernel nodes total.
// ============================================================================
#define GEMM_DSMEM (81920 + 2048)

extern "C" void kernel_launch(void* const* d_in, const int* in_sizes, int n_in,
                              void* d_out, int out_size)
{
    const float* x  = (const float*)d_in[0];   // [50000, 512]
    const int*   ei = (const int*)  d_in[1];   // [2, 800000]
    const float* W  = (const float*)d_in[2];   // [512, 128]
    const float* b  = (const float*)d_in[3];   // [128]
    const float* pw = (const float*)d_in[4];   // [128]
    float* out = (float*)d_out;                // [50000, 128]

    const int* src = ei;
    const int* dst = ei + NEDGES;

    static cudaStream_t s2 = nullptr;
    static cudaEvent_t evFork = nullptr, evJoin = nullptr;
    if (s2 == nullptr) {
        cudaStreamCreateWithFlags(&s2, cudaStreamNonBlocking);
        cudaEventCreateWithFlags(&evFork, cudaEventDisableTiming);
        cudaEventCreateWithFlags(&evJoin, cudaEventDisableTiming);
        cudaFuncSetAttribute(gemm_tc_kernel,
                             cudaFuncAttributeMaxDynamicSharedMemorySize, GEMM_DSMEM);
    }

    // Fork: fused CSR build on s2
    cudaEventRecord(evFork, 0);
    cudaStreamWaitEvent(s2, evFork, 0);

    csr_kernel<<<CSR_BLOCKS, 256, 0, s2>>>(src, dst);
    cudaEventRecord(evJoin, s2);

    // Main stream: W -> fp16 pack, then fp16 tensor-core GEMM
    wprep_kernel<<<(WB_U32 + 255) / 256, 256>>>(W);
    gemm_tc_kernel<<<N_TILES, 256, GEMM_DSMEM>>>(x);

    // Join, then aggregate (needs both h and CSR)
    cudaStreamWaitEvent(0, evJoin, 0);
    aggregate_kernel<<<(NNODES * 32 + 255) / 256, 256>>>(b, pw, out);
}

// round 13
// speedup vs baseline: 1.2609x; 1.2609x over previous
#include <cuda_runtime.h>
#include <cuda_bf16.h>
#include <cuda_fp16.h>
#include <stdint.h>

// Problem constants (fixed by the reference)
#define NNODES 50000
#define NEDGES 800000
#define KDIM   512
#define HDIM   128

#define SCAN_BLK 256
#define N_SCAN_BLOCKS ((NNODES + SCAN_BLK - 1) / SCAN_BLK)   // 196

#define BK 32
#define KB_ITERS (KDIM / BK)           // 16
#define N_TILES ((NNODES + 127) / 128) // 391
#define WB_U32  (KB_ITERS * 2048)      // W fp16 tiles: 16 x 8KB = 32K u32

// ---------------- device scratch (no allocs allowed) ----------------
__device__ uint32_t g_h2[NNODES * 64];      // h = x @ W, fp16 half2-packed
__device__ int      g_cnt[NNODES];          // zeroed by scan for next run
__device__ int      g_off[NNODES + 1];
__device__ int      g_cursor[NNODES];       // zeroed by scan for next run
__device__ int      g_srcs[NEDGES];
__device__ float    g_dinv[NNODES];
__device__ int      g_bsum[N_SCAN_BLOCKS];
__device__ int      g_done;                 // grid-barrier counter (reset by hist)
// W as fp16, per-kb tiles [n=128][64B row: k0-31], SW64-swizzled:
__device__ uint32_t g_Wb[WB_U32];

// ======================= PTX helpers (baseline compute_103-safe) ==========
__device__ __forceinline__ uint32_t smem_u32(const void* p) {
    uint32_t a;
    asm("{ .reg .u64 t; cvta.to.shared.u64 t, %1; cvt.u32.u64 %0, t; }"
        : "=r"(a) : "l"(p));
    return a;
}
__device__ __forceinline__ uint32_t sw64(uint32_t off) {
    return off ^ ((off >> 3) & 0x30);
}
__device__ __forceinline__ void ldsm_x4(uint32_t& r0, uint32_t& r1,
                                        uint32_t& r2, uint32_t& r3, uint32_t addr) {
    asm volatile("ldmatrix.sync.aligned.m8n8.x4.shared.b16 {%0,%1,%2,%3}, [%4];"
        : "=r"(r0), "=r"(r1), "=r"(r2), "=r"(r3) : "r"(addr));
}
__device__ __forceinline__ void mma_fp16(float* c, const uint32_t* a,
                                         uint32_t b0, uint32_t b1) {
    asm volatile(
        "mma.sync.aligned.m16n8k16.row.col.f32.f16.f16.f32 "
        "{%0,%1,%2,%3}, {%4,%5,%6,%7}, {%8,%9}, {%0,%1,%2,%3};"
        : "+f"(c[0]), "+f"(c[1]), "+f"(c[2]), "+f"(c[3])
        : "r"(a[0]), "r"(a[1]), "r"(a[2]), "r"(a[3]), "r"(b0), "r"(b1));
}
__device__ __forceinline__ void cp_async16(uint32_t smem_dst, const void* gsrc) {
    asm volatile("cp.async.cg.shared.global [%0], [%1], 16;"
        :: "r"(smem_dst), "l"(gsrc) : "memory");
}
__device__ __forceinline__ void cp_async16_z(uint32_t smem_dst, const void* gsrc,
                                             uint32_t srcsz) {
    asm volatile("cp.async.cg.shared.global [%0], [%1], 16, %2;"
        :: "r"(smem_dst), "l"(gsrc), "r"(srcsz) : "memory");
}
#define CP_COMMIT() asm volatile("cp.async.commit_group;" ::: "memory")
#define CP_WAIT(n)  asm volatile("cp.async.wait_group %0;" :: "n"(n) : "memory")
__device__ __forceinline__ uint4 lds128(uint32_t a) {
    uint4 v;
    asm volatile("ld.shared.v4.u32 {%0,%1,%2,%3}, [%4];"
        : "=r"(v.x), "=r"(v.y), "=r"(v.z), "=r"(v.w) : "r"(a));
    return v;
}
__device__ __forceinline__ void sts128u(uint32_t a, uint4 v) {
    asm volatile("st.shared.v4.u32 [%0], {%1,%2,%3,%4};"
        :: "r"(a), "r"(v.x), "r"(v.y), "r"(v.z), "r"(v.w) : "memory");
}
__device__ __forceinline__ uint32_t f16x2_rn(float lo, float hi) {
    uint32_t r;
    asm("cvt.rn.f16x2.f32 %0, %1, %2;" : "=r"(r) : "f"(hi), "f"(lo));
    return r;
}

// ============================================================================
// Kernel 0: W -> fp16 tiles, per-kb [n=128][64B: k0-31], SW64-swizzled.
// ============================================================================
__global__ __launch_bounds__(256)
void wprep_kernel(const float* __restrict__ W)
{
    int o = blockIdx.x * blockDim.x + threadIdx.x;
    if (o >= WB_U32) return;
    int kb = o >> 11;
    uint32_t byte = (o & 2047) * 4;
    uint32_t un = sw64(byte);
    int n = un >> 6;
    int i = (un & 63) >> 2;
    int k0 = kb * BK + 2 * i;
    float w0 = W[(size_t)k0 * HDIM + n];
    float w1 = W[(size_t)(k0 + 1) * HDIM + n];
    g_Wb[o] = f16x2_rn(w0, w1);
}

// ============================================================================
// Kernel 1: fp16 GEMM via mma.sync m16n8k16 (f32 accumulate).
// CTA 128x128, 256 threads, warp tile 32x64. 3-stage cp.async pipeline
// (82 KB SMEM -> 2 CTAs/SM — round-9 known-good configuration, unchanged).
// ============================================================================
__global__ __launch_bounds__(256, 2)
void gemm_tc_kernel(const float* __restrict__ X)
{
    extern __shared__ char dsm[];
    const uint32_t base = (smem_u32(dsm) + 1023u) & ~1023u;
    uint32_t RA[3] = { base, base + 16384, base + 32768 };       // raw f32 stages
    uint32_t BB[3] = { base + 49152, base + 57344, base + 65536 }; // fp16 W stages
    const uint32_t AB = base + 73728;                             // fp16 A tile

    const int tid  = threadIdx.x;
    const int lane = tid & 31;
    const int wid  = tid >> 5;
    const int wm   = wid >> 1;
    const int wn   = wid & 1;
    const int brow = blockIdx.x * 128;

    // ---- raw-A cp.async assignment: 4 x 16B per thread (SW128 rows) ----
    uint32_t a_dst[4];
    const float* a_srcb[4];
    uint32_t a_sz[4];
    #pragma unroll
    for (int i = 0; i < 4; i++) {
        int idx = tid + i * 256;
        int row = idx >> 3;
        int q   = idx & 7;
        a_dst[i]  = (uint32_t)row * 128 + ((uint32_t)(q ^ (row & 7)) << 4);
        a_srcb[i] = X + (size_t)(brow + row) * KDIM + q * 4;
        a_sz[i]   = ((brow + row) < NNODES) ? 16u : 0u;
    }

    // ---- convert-pass assignment: 2 output 16B groups per thread ----
    uint32_t c_src[2][2], c_dst[2];
    #pragma unroll
    for (int i = 0; i < 2; i++) {
        int slot = tid + i * 256;
        int row  = slot >> 2;
        int og   = slot & 3;
        uint32_t rx = (uint32_t)(row & 7);
        c_src[i][0] = (uint32_t)row * 128 + (((uint32_t)(2 * og)     ^ rx) << 4);
        c_src[i][1] = (uint32_t)row * 128 + (((uint32_t)(2 * og + 1) ^ rx) << 4);
        c_dst[i]    = (uint32_t)row * 64 +
                      (((uint32_t)og ^ ((uint32_t)(row >> 1) & 3)) << 4);
    }

    // ---- ldmatrix address precompute (64B rows, SW64) ----
    uint32_t a_rb[2], a_rx[2];
    #pragma unroll
    for (int mf = 0; mf < 2; mf++) {
        uint32_t row = wm * 32 + mf * 16 + (lane & 15);
        a_rb[mf] = row * 64;
        a_rx[mf] = (row >> 1) & 3;
    }
    const uint32_t a_cbase = (uint32_t)(lane >> 4);
    uint32_t b_rb[4], b_rx[4];
    #pragma unroll
    for (int p = 0; p < 4; p++) {
        uint32_t n = wn * 64 + p * 16 + ((lane >> 4) << 3) + (lane & 7);
        b_rb[p] = n * 64;
        b_rx[p] = (n >> 1) & 3;
    }
    const uint32_t b_cbase = (uint32_t)((lane >> 3) & 1);

    float acc[2][8][4];
    #pragma unroll
    for (int mf = 0; mf < 2; mf++)
        #pragma unroll
        for (int nf = 0; nf < 8; nf++)
            #pragma unroll
            for (int j = 0; j < 4; j++) acc[mf][nf][j] = 0.f;

    // ---- stage helper (stage s into buffer s%3), one commit per stage ----
    auto stage = [&](int s) {
        uint32_t ra = RA[s % 3], bb = BB[s % 3];
        const uint32_t* wb = g_Wb + (size_t)s * 2048;
        #pragma unroll
        for (int i = 0; i < 4; i++)
            cp_async16_z(ra + a_dst[i], a_srcb[i] + s * BK, a_sz[i]);
        #pragma unroll
        for (int i = 0; i < 2; i++) {
            int idx = tid + i * 256;
            cp_async16(bb + idx * 16, wb + idx * 4);
        }
        CP_COMMIT();
    };

    // ---- prologue: stages 0 and 1 in flight ----
    stage(0);
    stage(1);

    for (int kb = 0; kb < KB_ITERS; kb++) {
        if (kb + 1 < KB_ITERS) { CP_WAIT(1); } else { CP_WAIT(0); }
        __syncthreads();   // stage kb visible; AB free (prev compute done)

        const uint32_t RAc = RA[kb % 3];
        const uint32_t BBc = BB[kb % 3];

        // ---- convert raw f32 -> fp16 tile AB ----
        #pragma unroll
        for (int i = 0; i < 2; i++) {
            uint4 a = lds128(RAc + c_src[i][0]);
            uint4 b = lds128(RAc + c_src[i][1]);
            uint4 o;
            o.x = f16x2_rn(__uint_as_float(a.x), __uint_as_float(a.y));
            o.y = f16x2_rn(__uint_as_float(a.z), __uint_as_float(a.w));
            o.z = f16x2_rn(__uint_as_float(b.x), __uint_as_float(b.y));
            o.w = f16x2_rn(__uint_as_float(b.z), __uint_as_float(b.w));
            sts128u(AB + c_dst[i], o);
        }
        __syncthreads();   // AB visible; RA[kb] reads done

        // ---- keep 2 stages in flight ----
        if (kb + 2 < KB_ITERS) stage(kb + 2);

        // ---- compute: 2 k16-steps, single fp16 pass ----
        #pragma unroll
        for (int s = 0; s < 2; s++) {
            uint32_t ah[2][4];
            #pragma unroll
            for (int mf = 0; mf < 2; mf++) {
                uint32_t g = (uint32_t)(s * 2) + a_cbase;
                uint32_t off = a_rb[mf] + ((g ^ a_rx[mf]) << 4);
                ldsm_x4(ah[mf][0], ah[mf][1], ah[mf][2], ah[mf][3], AB + off);
            }
            #pragma unroll
            for (int p = 0; p < 4; p++) {
                uint32_t g = (uint32_t)(s * 2) + b_cbase;
                uint32_t off = b_rb[p] + ((g ^ b_rx[p]) << 4);
                uint32_t bh[4];
                ldsm_x4(bh[0], bh[1], bh[2], bh[3], BBc + off);
                #pragma unroll
                for (int j = 0; j < 2; j++) {
                    #pragma unroll
                    for (int mf = 0; mf < 2; mf++)
                        mma_fp16(acc[mf][p * 2 + j], ah[mf],
                                 bh[2 * j], bh[2 * j + 1]);
                }
            }
        }
    }

    // ---- epilogue: accum regs -> g_h2 (fp16 half2-packed) ----
    half2* H2 = (half2*)g_h2;
    #pragma unroll
    for (int mf = 0; mf < 2; mf++) {
        int row0 = brow + wm * 32 + mf * 16 + (lane >> 2);
        #pragma unroll
        for (int nf = 0; nf < 8; nf++) {
            int c2 = wn * 32 + nf * 4 + (lane & 3);
            if (row0 < NNODES)
                H2[(size_t)row0 * 64 + c2] =
                    __floats2half2_rn(acc[mf][nf][0], acc[mf][nf][1]);
            if (row0 + 8 < NNODES)
                H2[(size_t)(row0 + 8) * 64 + c2] =
                    __floats2half2_rn(acc[mf][nf][2], acc[mf][nf][3]);
        }
    }
}

// ============================================================================
// Kernel 2: histogram (also resets the scan grid-barrier counter)
// ============================================================================
__global__ void hist_kernel(const int* __restrict__ dst)
{
    int e = blockIdx.x * blockDim.x + threadIdx.x;
    if (e == 0) g_done = 0;
    if (e < NEDGES) atomicAdd(&g_cnt[dst[e]], 1);
}

// ============================================================================
// Kernel 3: fused scan (local scan + grid barrier + apply) + dinv + cleanup.
// ============================================================================
__global__ __launch_bounds__(SCAN_BLK)
void scan_kernel()
{
    __shared__ int sh[SCAN_BLK];
    __shared__ int red[SCAN_BLK];
    const int t   = threadIdx.x;
    const int blk = blockIdx.x;
    const int i   = blk * SCAN_BLK + t;

    int v = 0;
    if (i < NNODES) {
        v = g_cnt[i];
        g_dinv[i]   = rsqrtf((float)(v + 1));
        g_cnt[i]    = 0;
        g_cursor[i] = 0;
    }

    sh[t] = v;
    __syncthreads();
    #pragma unroll
    for (int d = 1; d < SCAN_BLK; d <<= 1) {
        int u = (t >= d) ? sh[t - d] : 0;
        __syncthreads();
        sh[t] += u;
        __syncthreads();
    }
    int local_excl = sh[t] - v;

    if (t == SCAN_BLK - 1) g_bsum[blk] = sh[t];
    __threadfence();
    __syncthreads();
    if (t == 0) {
        atomicAdd(&g_done, 1);
        volatile int* dp = &g_done;
        while (*dp < N_SCAN_BLOCKS) { }
    }
    __syncthreads();
    __threadfence();

    red[t] = (t < blk) ? g_bsum[t] : 0;
    __syncthreads();
    #pragma unroll
    for (int d = SCAN_BLK / 2; d > 0; d >>= 1) {
        if (t < d) red[t] += red[t + d];
        __syncthreads();
    }
    if (i < NNODES) g_off[i] = local_excl + red[0];
    if (i == 0) g_off[NNODES] = NEDGES;
}

// ============================================================================
// Kernel 4: fill CSR
// ============================================================================
__global__ void fill_kernel(const int* __restrict__ src, const int* __restrict__ dst)
{
    int e = blockIdx.x * blockDim.x + threadIdx.x;
    if (e >= NEDGES) return;
    int d = dst[e];
    int p = atomicAdd(&g_cursor[d], 1);
    g_srcs[g_off[d] + p] = src[e];
}

// ============================================================================
// Kernel 5: aggregate + bias + PReLU. One warp per node, fp16 gather.
// 8-wide unrolled body (8 h-row gathers in flight) for latency hiding.
// ============================================================================
__device__ __forceinline__ float4 h4_at(const uint2* h2, int node, int lane)
{
    uint2 v = h2[(size_t)node * 32 + lane];
    float2 f = __half22float2(*(const half2*)&v.x);
    float2 g = __half22float2(*(const half2*)&v.y);
    return make_float4(f.x, f.y, g.x, g.y);
}

__global__ __launch_bounds__(256)
void aggregate_kernel(const float* __restrict__ b,
                      const float* __restrict__ pw,
                      float* __restrict__ out)
{
    int gwarp = (blockIdx.x * blockDim.x + threadIdx.x) >> 5;
    int lane  = threadIdx.x & 31;
    if (gwarp >= NNODES) return;

    const uint2* h2 = (const uint2*)g_h2;
    const int n = gwarp;

    float di = g_dinv[n];
    float4 hn = h4_at(h2, n, lane);

    float4 acc = make_float4(0.f, 0.f, 0.f, 0.f);
    int s = g_off[n];
    int e = g_off[n + 1];
    int i = s;

    // 8-wide body: 8 gathers + 8 broadcast weights in flight
    for (; i + 7 < e; i += 8) {
        int u[8];
        float w[8];
        #pragma unroll
        for (int j = 0; j < 8; j++) u[j] = g_srcs[i + j];
        #pragma unroll
        for (int j = 0; j < 8; j++) w[j] = g_dinv[u[j]];
        float4 v[8];
        #pragma unroll
        for (int j = 0; j < 8; j++) v[j] = h4_at(h2, u[j], lane);
        #pragma unroll
        for (int j = 0; j < 8; j++) {
            acc.x += v[j].x * w[j];
            acc.y += v[j].y * w[j];
            acc.z += v[j].z * w[j];
            acc.w += v[j].w * w[j];
        }
    }
    // 4-wide secondary
    for (; i + 3 < e; i += 4) {
        int u0 = g_srcs[i];
        int u1 = g_srcs[i + 1];
        int u2 = g_srcs[i + 2];
        int u3 = g_srcs[i + 3];
        float w0 = g_dinv[u0], w1 = g_dinv[u1];
        float w2 = g_dinv[u2], w3 = g_dinv[u3];
        float4 v0 = h4_at(h2, u0, lane);
        float4 v1 = h4_at(h2, u1, lane);
        float4 v2 = h4_at(h2, u2, lane);
        float4 v3 = h4_at(h2, u3, lane);
        acc.x += v0.x * w0 + v1.x * w1 + v2.x * w2 + v3.x * w3;
        acc.y += v0.y * w0 + v1.y * w1 + v2.y * w2 + v3.y * w3;
        acc.z += v0.z * w0 + v1.z * w1 + v2.z * w2 + v3.z * w3;
        acc.w += v0.w * w0 + v1.w * w1 + v2.w * w2 + v3.w * w3;
    }
    // scalar tail
    for (; i < e; i++) {
        int u = g_srcs[i];
        float w = g_dinv[u];
        float4 v = h4_at(h2, u, lane);
        acc.x += v.x * w; acc.y += v.y * w; acc.z += v.z * w; acc.w += v.w * w;
    }

    float s2 = di * di;
    float4 bb = ((const float4*)b)[lane];
    float4 pp = ((const float4*)pw)[lane];
    float4 r;
    r.x = acc.x * di + hn.x * s2 + bb.x;
    r.y = acc.y * di + hn.y * s2 + bb.y;
    r.z = acc.z * di + hn.z * s2 + bb.z;
    r.w = acc.w * di + hn.w * s2 + bb.w;
    r.x = (r.x > 0.f) ? r.x : r.x * pp.x;
    r.y = (r.y > 0.f) ? r.y : r.y * pp.y;
    r.z = (r.z > 0.f) ? r.z : r.z * pp.z;
    r.w = (r.w > 0.f) ? r.w : r.w * pp.w;

    ((float4*)out)[(size_t)n * 32 + lane] = r;
}

// ============================================================================
// Launch: 6 kernel nodes total (round-9 structure).
// ============================================================================
#define GEMM_DSMEM (81920 + 2048)

extern "C" void kernel_launch(void* const* d_in, const int* in_sizes, int n_in,
                              void* d_out, int out_size)
{
    const float* x  = (const float*)d_in[0];   // [50000, 512]
    const int*   ei = (const int*)  d_in[1];   // [2, 800000]
    const float* W  = (const float*)d_in[2];   // [512, 128]
    const float* b  = (const float*)d_in[3];   // [128]
    const float* pw = (const float*)d_in[4];   // [128]
    float* out = (float*)d_out;                // [50000, 128]

    const int* src = ei;
    const int* dst = ei + NEDGES;

    static cudaStream_t s2 = nullptr;
    static cudaEvent_t evFork = nullptr, evJoin = nullptr;
    if (s2 == nullptr) {
        cudaStreamCreateWithFlags(&s2, cudaStreamNonBlocking);
        cudaEventCreateWithFlags(&evFork, cudaEventDisableTiming);
        cudaEventCreateWithFlags(&evJoin, cudaEventDisableTiming);
        cudaFuncSetAttribute(gemm_tc_kernel,
                             cudaFuncAttributeMaxDynamicSharedMemorySize, GEMM_DSMEM);
    }

    // Fork: CSR-build chain on s2
    cudaEventRecord(evFork, 0);
    cudaStreamWaitEvent(s2, evFork, 0);

    hist_kernel<<<(NEDGES + 255) / 256, 256, 0, s2>>>(dst);
    scan_kernel<<<N_SCAN_BLOCKS, SCAN_BLK, 0, s2>>>();
    fill_kernel<<<(NEDGES + 255) / 256, 256, 0, s2>>>(src, dst);
    cudaEventRecord(evJoin, s2);

    // Main stream: W -> fp16 pack, then fp16 tensor-core GEMM
    wprep_kernel<<<(WB_U32 + 255) / 256, 256>>>(W);
    gemm_tc_kernel<<<N_TILES, 256, GEMM_DSMEM>>>(x);

    // Join, then aggregate (needs both h and CSR)
    cudaStreamWaitEvent(0, evJoin, 0);
    aggregate_kernel<<<(NNODES * 32 + 255) / 256, 256>>>(b, pw, out);
}